// round 16
// baseline (speedup 1.0000x reference)
#include <cuda_runtime.h>
#include <cfloat>
#include <stdint.h>

#define BS    8
#define NQ    16384
#define NG    1024
#define TOPK  4
#define NBIN  1024
#define BINW  0.0009765625f     // 1/1024
#define NQP   (NQ + 192)        // padded candidate row
#define NTOT  (BS * NQ)         // 131072
#define NBG   (BS * NG)         // 8192
#define COST_POINT 0.1f
#define REG_COEF   5.0f

// -------- scratch (static device globals) --------
__device__ float4 g_packed[NTOT];          // {-2x, -2y, |p|^2, prob0}
__device__ float  g_prob[NTOT];
__device__ unsigned char g_flag[NTOT];
__device__ int    g_hist[BS][NBIN];        // zeroed at load; re-zeroed by scatter
__device__ float4 g_cand4[BS][NQP];        // candidates, descending-prob bucket order
__device__ int    g_candq[BS][NQP];
__device__ int    g_pos[BS][NBIN];         // bucket write cursors (init = bases)
__device__ int    g_tbin[BS];
__device__ int    g_ncand[BS];
__device__ float  g_regp[NBG];
__device__ float  g_part[3 * 128];
__device__ int    g_done;                  // reduce last-block counter
__device__ int    g_pdone;                 // prep last-block counter
__device__ int    g_mi32;

__device__ __forceinline__ int mask_at(const void* m, int i, int is_i32) {
    return is_i32 ? (((const int*)m)[i] != 0) : (((const unsigned char*)m)[i] != 0);
}

// -------- prep: per-(b,q) precompute + hist atomics + zeros + mask detect,
//          with setup (prefix / p4 threshold / bucket bases) FUSED into the
//          last block via threadfence+atomic counter --------
__global__ void __launch_bounds__(256) prep_kernel(
    const float* __restrict__ pc, const float* __restrict__ pl,
    const unsigned char* __restrict__ m)
{
    int t = threadIdx.x;
    if (blockIdx.x == 0) {
        int bad = ((t & 3) != 0) && (m[t] != 0);
        int any = __syncthreads_or(bad);
        if (t == 0) { g_mi32 = !any; g_done = 0; }
    }
    int i = blockIdx.x * 256 + t;          // grid is exactly NTOT/256 blocks
    float2 c  = ((const float2*)pc)[i];
    float2 lg = ((const float2*)pl)[i];
    float x = c.x, y = c.y, l0 = lg.x, l1 = lg.y;
    float mm = fmaxf(l0, l1);
    float e0 = expf(l0 - mm);
    float e1 = expf(l1 - mm);
    float s  = __fadd_rn(e0, e1);
    float p0 = __fdiv_rn(e0, s);
    float pp = __fadd_rn(__fmul_rn(x, x), __fmul_rn(y, y));
    g_packed[i] = make_float4(__fmul_rn(-2.0f, x), __fmul_rn(-2.0f, y), pp, p0);
    g_prob[i] = p0;
    g_flag[i] = 0;
    if (i < NBG) g_regp[i] = 0.0f;
    int bin = min(NBIN - 1, (int)(p0 * 1024.0f));
    atomicAdd(&g_hist[i >> 14][bin], 1);

    // ---- last-block setup ----
    __threadfence();
    __syncthreads();
    __shared__ bool s_last;
    if (t == 0) s_last = (atomicAdd(&g_pdone, 1) == (NTOT / 256) - 1);
    __syncthreads();
    if (!s_last) return;

    __shared__ int ls[256];
    __shared__ int p4bin;
    __shared__ int stbin;
    for (int b = 0; b < BS; b++) {
        if (t == 0) p4bin = 0;
        __syncthreads();
        // thread t owns bins [4t..4t+3]; suffix sums S[i] = sum_{j>=i} hist[j]
        int h0 = g_hist[b][4 * t], h1 = g_hist[b][4 * t + 1];
        int h2 = g_hist[b][4 * t + 2], h3 = g_hist[b][4 * t + 3];
        ls[t] = h0 + h1 + h2 + h3;
        __syncthreads();
        for (int o = 1; o < 256; o <<= 1) {
            int v = (t + o < 256) ? ls[t + o] : 0;
            __syncthreads();
            ls[t] += v;
            __syncthreads();
        }
        int excl = (t + 1 < 256) ? ls[t + 1] : 0;   // sum over threads > t
        int S3 = excl + h3;
        int S2 = S3 + h2;
        int S1 = S2 + h1;
        int S0 = S1 + h0;
        // p4bin = max bin with S[bin] >= 4
        int cand = -1;
        if      (S3 >= 4) cand = 4 * t + 3;
        else if (S2 >= 4) cand = 4 * t + 2;
        else if (S1 >= 4) cand = 4 * t + 1;
        else if (S0 >= 4) cand = 4 * t;
        if (cand >= 0) atomicMax(&p4bin, cand);
        __syncthreads();
        if (t == 0) {
            float lo4 = (float)p4bin * BINW;         // lower bound on p4
            float thresh = lo4 - 0.141422f;          // p4 - 0.1*sqrt(2), conservative
            int tb = (int)floorf(thresh * 1024.0f);
            if (tb < 0) tb = 0;
            stbin = tb;
            g_tbin[b] = tb;
        }
        __syncthreads();
        int tb = stbin;
        // bucket base (descending order): base[bin] = S[bin+1]
        if (4 * t     >= tb) g_pos[b][4 * t]     = S1;
        if (4 * t + 1 >= tb) g_pos[b][4 * t + 1] = S2;
        if (4 * t + 2 >= tb) g_pos[b][4 * t + 2] = S3;
        if (4 * t + 3 >= tb) g_pos[b][4 * t + 3] = excl;
        if (tb >= 4 * t && tb <= 4 * t + 3) {
            int Stb = (tb == 4 * t) ? S0 : (tb == 4 * t + 1) ? S1
                    : (tb == 4 * t + 2) ? S2 : S3;
            g_ncand[b] = Stb;
        }
        __syncthreads();   // ls/p4bin reuse in next batch iteration
    }
}

// -------- scatter: counting-sort into descending buckets + counter re-zero + pads
__global__ void __launch_bounds__(256) scatter_kernel() {
    int i = blockIdx.x * 256 + threadIdx.x;
    // re-zero histogram + prep counter for the next graph replay
    if (i < BS * NBIN) ((int*)g_hist)[i] = 0;
    if (i == BS * NBIN) g_pdone = 0;
    // sentinel padding: w=-1e30 is provably rejected by the filter & break
    if (blockIdx.x < BS && threadIdx.x < 192) {
        int b = blockIdx.x;
        int idx = g_ncand[b] + threadIdx.x;
        g_cand4[b][idx] = make_float4(0.0f, 0.0f, 0.0f, -1e30f);
        g_candq[b][idx] = 0;
    }
    int b = i >> 14;
    float p = g_prob[i];
    int bin = min(NBIN - 1, (int)(p * 1024.0f));
    if (bin >= g_tbin[b]) {
        int slot = atomicAdd(&g_pos[b][bin], 1);
        g_cand4[b][slot] = g_packed[i];
        g_candq[b][slot] = i & (NQ - 1);
    }
}

// orderable-uint mapping and inverse
__device__ __forceinline__ unsigned int float_key(float f) {
    unsigned int u = __float_as_uint(f);
    return u ^ (((int)u < 0) ? 0xFFFFFFFFu : 0x80000000u);
}
__device__ __forceinline__ float key_to_float(unsigned int k) {
    return __uint_as_float(k ^ ((k & 0x80000000u) ? 0x80000000u : 0xFFFFFFFFu));
}

#define KEY_SENTINEL 0xFF7FFFFFFFFFFFFFull   // (float_key(FLT_MAX)<<32) | 0xFFFFFFFF

// snapshot-exchange merge with DEDUP insert: skips keys equal to any current
// entry, so overlapping lists (shared phase-1 prefix) merge correctly.
// Proof of exactness: if global-top-4 key X is displaced from a lane's list,
// that lane holds 4 keys < X, which propagate into the merged result; hence
// the merged list is exactly the top-4 of the union of all lane lists.
#define DEDUP_MERGE(d)                                                         \
    {                                                                          \
        unsigned long long s0 = k0, s1 = k1, s2 = k2, s3 = k3;                 \
        unsigned long long p0 = __shfl_xor_sync(0xFFFFFFFFu, s0, d);           \
        unsigned long long p1 = __shfl_xor_sync(0xFFFFFFFFu, s1, d);           \
        unsigned long long p2 = __shfl_xor_sync(0xFFFFFFFFu, s2, d);           \
        unsigned long long p3 = __shfl_xor_sync(0xFFFFFFFFu, s3, d);           \
        unsigned long long ps[4] = {p0, p1, p2, p3};                           \
        _Pragma("unroll")                                                      \
        for (int r = 0; r < 4; r++) {                                          \
            unsigned long long pk = ps[r];                                     \
            if (pk < k3 && pk != k0 && pk != k1 && pk != k2) {                 \
                if (pk < k0)      { k3 = k2; k2 = k1; k1 = k0; k0 = pk; }      \
                else if (pk < k1) { k3 = k2; k2 = k1; k1 = pk; }               \
                else if (pk < k2) { k3 = k2; k2 = pk; }                        \
                else              { k3 = pk; }                                 \
            }                                                                  \
        }                                                                      \
    }

// evaluate one candidate f at index idx (sqrt-free filter + exact cost)
#define EVAL_CAND(f, idx)                                                      \
    {                                                                          \
        float h = __fmaf_rn((f).x, gx, __fmaf_rn((f).y, gy, (f).z));           \
        float u = __fmaf_rn(10.0f, (f).w, T);                                  \
        float v = __fmaf_rn(u, fabsf(u), -gg);                                 \
        if (h < v) {                                                           \
            float xx = __fmul_rn(-0.5f, (f).x), yy = __fmul_rn(-0.5f, (f).y);  \
            float d  = __fmaf_rn(yy, gy, __fmul_rn(xx, gx));                   \
            float s1 = __fadd_rn((f).z, gg);                                   \
            float sq = __fmaf_rn(-2.0f, d, s1);                                \
            float cost = __fadd_rn(                                            \
                __fmul_rn(COST_POINT, __fsqrt_rn(fmaxf(sq, 0.0f))), -(f).w);   \
            unsigned long long key =                                           \
                ((unsigned long long)float_key(cost) << 32)                    \
                | (unsigned int)__ldg(&candq[idx]);                            \
            if (key < k3) {                                                    \
                if (key < k0)      { k3 = k2; k2 = k1; k1 = k0; k0 = key; }    \
                else if (key < k1) { k3 = k2; k2 = k1; k1 = key; }             \
                else if (key < k2) { k3 = k2; k2 = key; }                      \
                else               { k3 = key; }                               \
                c3  = key_to_float((unsigned int)(k3 >> 32));                  \
                T   = __fmaf_rn(10.0f, c3, 1e-3f);                             \
                brk = __fadd_rn(-c3, -BINW);                                   \
            }                                                                  \
        }                                                                      \
    }

// -------- match: phase-1 (first 128 candidates, full merge -> tight global c3)
// then fully-independent per-lane scan (no shuffles), final dedup merge.
__global__ void __launch_bounds__(256) match_kernel(
    const float* __restrict__ pc,
    const float* __restrict__ gtc, const void* __restrict__ gtm)
{
    int blk = blockIdx.x;                 // 512 blocks: b*64 + sub
    int b   = blk >> 6;
    int sub = blk & 63;
    int t   = threadIdx.x;
    int par = t & 15;
    int g   = sub * 16 + (t >> 4);
    int bg  = b * NG + g;
    int active = mask_at(gtm, bg, g_mi32);
    int n = g_ncand[b];
    const float4* __restrict__ cand  = g_cand4[b];
    const int*    __restrict__ candq = g_candq[b];

    float2 gc = ((const float2*)gtc)[bg];
    float gx = gc.x, gy = gc.y;
    float gg = __fadd_rn(__fmul_rn(gx, gx), __fmul_rn(gy, gy));

    unsigned long long k0 = KEY_SENTINEL, k1 = KEY_SENTINEL,
                       k2 = KEY_SENTINEL, k3 = KEY_SENTINEL;
    float c3  = FLT_MAX;
    float T   = __fmaf_rn(10.0f, c3, 1e-3f);   // +inf: accept-all until filled
    float brk = -FLT_MAX;

    // ---- phase 1: window [0,128) — 8 candidates per lane
    {
        float4 fs[8];
        #pragma unroll
        for (int j = 0; j < 8; j++) fs[j] = __ldg(&cand[par + 16 * j]);
        if (active) {
            #pragma unroll
            for (int j = 0; j < 8; j++) EVAL_CAND(fs[j], par + 16 * j);
        }
    }
    // full merge: every lane now holds the exact global top-4 of window 0
    DEDUP_MERGE(1);
    DEDUP_MERGE(2);
    DEDUP_MERGE(4);
    DEDUP_MERGE(8);
    c3  = key_to_float((unsigned int)(k3 >> 32));
    T   = __fmaf_rn(10.0f, c3, 1e-3f);
    brk = __fadd_rn(-c3, -BINW);

    // ---- phase 2: independent per-lane scan, batches of 4, private break
    if (active) {
        for (int i = 128 + par; i < n; i += 64) {
            float4 f0 = __ldg(&cand[i]);
            float4 f1 = __ldg(&cand[i + 16]);
            float4 f2 = __ldg(&cand[i + 32]);
            float4 f3 = __ldg(&cand[i + 48]);
            // descending prob (granularity BINW): all elements after i have
            // prob < f0.w + BINW; if f0.w < brk they are all provably out.
            if (f0.w < brk) break;
            EVAL_CAND(f0, i);
            EVAL_CAND(f1, i + 16);
            EVAL_CAND(f2, i + 32);
            EVAL_CAND(f3, i + 48);
        }
    }

    // ---- final dedup merge of the 16 per-lane lists (overlap-safe)
    DEDUP_MERGE(1);
    DEDUP_MERGE(2);
    DEDUP_MERGE(4);
    DEDUP_MERGE(8);

    if (active && par == 0) {
        float acc = 0.0f;
        unsigned long long ks[4] = {k0, k1, k2, k3};
        #pragma unroll
        for (int k = 0; k < TOPK; k++) {
            int q = (int)(unsigned int)(ks[k] & 0xFFFFFFFFull);
            g_flag[b * NQ + q] = 1;          // idempotent; races benign
            float2 p = ((const float2*)pc)[b * NQ + q];   // exact coords
            float dx = __fadd_rn(p.x, -gx), dy = __fadd_rn(p.y, -gy);
            acc = __fadd_rn(acc, __fadd_rn(__fmul_rn(dx, dx), __fmul_rn(dy, dy)));
        }
        g_regp[bg] = acc;
    }
}

// -------- reduce: per-block partials (log-softmax recomputed inline)
//          + last-block fixed-order finale --------
__global__ void __launch_bounds__(256) reduce_kernel(
    const float* __restrict__ pl, const void* __restrict__ gtm,
    float* __restrict__ out)
{
    int blk = blockIdx.x;
    int base = blk * 1024;
    int t = threadIdx.x;
    int mi32 = g_mi32;

    float cl = 0.0f, rg = 0.0f; int cn = 0;
    #pragma unroll
    for (int j = 0; j < 4; j++) {
        int i = base + j * 256 + t;
        float2 lg = ((const float2*)pl)[i];
        float l0 = lg.x, l1 = lg.y;
        float mm = fmaxf(l0, l1);
        float ls = logf(__fadd_rn(expf(l0 - mm), expf(l1 - mm)));
        float lsel = g_flag[i] ? l0 : l1;
        cl += __fadd_rn(__fadd_rn(lsel, -mm), -ls);
    }
    if (base < NBG) {
        #pragma unroll
        for (int j = 0; j < 4; j++) {
            int i = base + j * 256 + t;
            rg += g_regp[i];
            cn += mask_at(gtm, i, mi32);
        }
    }
    __shared__ float s1[256], s2[256];
    __shared__ int   s3[256];
    s1[t] = cl; s2[t] = rg; s3[t] = cn;
    __syncthreads();
    for (int s = 128; s > 0; s >>= 1) {
        if (t < s) { s1[t] += s1[t + s]; s2[t] += s2[t + s]; s3[t] += s3[t + s]; }
        __syncthreads();
    }
    __shared__ bool s_last;
    if (t == 0) {
        g_part[blk]       = s1[0];
        g_part[128 + blk] = s2[0];
        g_part[256 + blk] = (float)s3[0];
        __threadfence();
        int old = atomicAdd(&g_done, 1);
        s_last = (old == 127);
    }
    __syncthreads();
    if (s_last) {
        __shared__ float a[128], bb[128], cc[128];
        if (t < 128) {
            a[t]  = g_part[t];
            bb[t] = g_part[128 + t];
            cc[t] = g_part[256 + t];
        }
        __syncthreads();
        for (int s = 64; s > 0; s >>= 1) {
            if (t < s) { a[t] += a[t + s]; bb[t] += bb[t + s]; cc[t] += cc[t + s]; }
            __syncthreads();
        }
        if (t == 0) {
            float n_valid = __fmul_rn(cc[0], (float)TOPK);
            out[0] = __fmul_rn(__fdiv_rn(bb[0], __fmul_rn(n_valid, 2.0f)), REG_COEF);
            out[1] = __fdiv_rn(-a[0], (float)NTOT);
        }
    }
}

extern "C" void kernel_launch(void* const* d_in, const int* in_sizes, int n_in,
                              void* d_out, int out_size)
{
    (void)in_sizes; (void)n_in; (void)out_size;
    const float* pred_coords = (const float*)d_in[0];
    const float* pred_logits = (const float*)d_in[1];
    const float* gt_coords   = (const float*)d_in[2];
    const void*  gt_masks    = d_in[4];
    float* out = (float*)d_out;

    prep_kernel   <<<NTOT / 256, 256>>>(pred_coords, pred_logits,
                                        (const unsigned char*)gt_masks);
    scatter_kernel<<<NTOT / 256, 256>>>();
    match_kernel  <<<BS * 64, 256>>>(pred_coords, gt_coords, gt_masks);
    reduce_kernel <<<128, 256>>>(pred_logits, gt_masks, out);
}

// round 17
// speedup vs baseline: 1.2854x; 1.2854x over previous
#include <cuda_runtime.h>
#include <cfloat>
#include <stdint.h>

#define BS    8
#define NQ    16384
#define NG    1024
#define TOPK  4
#define NBIN  1024
#define BINW  0.0009765625f     // 1/1024
#define NQP   (NQ + 192)        // padded candidate row
#define NTOT  (BS * NQ)         // 131072
#define NBG   (BS * NG)         // 8192
#define NRED  512               // reduce blocks
#define COST_POINT 0.1f
#define REG_COEF   5.0f

// -------- scratch (static device globals) --------
__device__ float4 g_packed[NTOT];          // {-2x, -2y, |p|^2, prob0}
__device__ float  g_prob[NTOT];
__device__ unsigned char g_flag[NTOT];
__device__ int    g_hist[BS][NBIN];        // zeroed at load; re-zeroed by scatter
__device__ float4 g_cand4[BS][NQP];        // candidates, descending-prob bucket order
__device__ int    g_candq[BS][NQP];
__device__ int    g_pos[BS][NBIN];         // bucket write cursors (init = bases)
__device__ int    g_tbin[BS];
__device__ int    g_ncand[BS];
__device__ float  g_regp[NBG];
__device__ float  g_part[3 * NRED];
__device__ int    g_done;                  // reduce last-block counter
__device__ int    g_mi32;

__device__ __forceinline__ int mask_at(const void* m, int i, int is_i32) {
    return is_i32 ? (((const int*)m)[i] != 0) : (((const unsigned char*)m)[i] != 0);
}

// -------- prep: per-(b,q) precompute + hist atomics + zeros + mask detect ----
__global__ void __launch_bounds__(256) prep_kernel(
    const float* __restrict__ pc, const float* __restrict__ pl,
    const unsigned char* __restrict__ m)
{
    int t = threadIdx.x;
    if (blockIdx.x == 0) {
        int bad = ((t & 3) != 0) && (m[t] != 0);
        int any = __syncthreads_or(bad);
        if (t == 0) { g_mi32 = !any; g_done = 0; }
    }
    int i = blockIdx.x * 256 + t;
    float2 c  = ((const float2*)pc)[i];
    float2 lg = ((const float2*)pl)[i];
    float x = c.x, y = c.y, l0 = lg.x, l1 = lg.y;
    float mm = fmaxf(l0, l1);
    float e0 = expf(l0 - mm);
    float e1 = expf(l1 - mm);
    float s  = __fadd_rn(e0, e1);
    float p0 = __fdiv_rn(e0, s);
    float pp = __fadd_rn(__fmul_rn(x, x), __fmul_rn(y, y));
    g_packed[i] = make_float4(__fmul_rn(-2.0f, x), __fmul_rn(-2.0f, y), pp, p0);
    g_prob[i] = p0;
    g_flag[i] = 0;
    if (i < NBG) g_regp[i] = 0.0f;
    int bin = min(NBIN - 1, (int)(p0 * 1024.0f));
    atomicAdd(&g_hist[i >> 14][bin], 1);
}

// -------- setup: prefix over per-batch histogram, p4 threshold, bucket bases ----
__global__ void __launch_bounds__(256) setup_kernel() {
    int b = blockIdx.x;
    int t = threadIdx.x;
    __shared__ int ls[256];
    __shared__ int p4bin;
    __shared__ int stbin;
    if (t == 0) p4bin = 0;
    // thread t owns bins [4t..4t+3]; suffix sums S[i] = sum_{j>=i} hist[j]
    int h0 = g_hist[b][4 * t], h1 = g_hist[b][4 * t + 1];
    int h2 = g_hist[b][4 * t + 2], h3 = g_hist[b][4 * t + 3];
    ls[t] = h0 + h1 + h2 + h3;
    __syncthreads();
    for (int o = 1; o < 256; o <<= 1) {
        int v = (t + o < 256) ? ls[t + o] : 0;
        __syncthreads();
        ls[t] += v;
        __syncthreads();
    }
    int excl = (t + 1 < 256) ? ls[t + 1] : 0;   // sum over threads > t
    int S3 = excl + h3;
    int S2 = S3 + h2;
    int S1 = S2 + h1;
    int S0 = S1 + h0;
    // p4bin = max bin with S[bin] >= 4
    int cand = -1;
    if      (S3 >= 4) cand = 4 * t + 3;
    else if (S2 >= 4) cand = 4 * t + 2;
    else if (S1 >= 4) cand = 4 * t + 1;
    else if (S0 >= 4) cand = 4 * t;
    if (cand >= 0) atomicMax(&p4bin, cand);
    __syncthreads();
    if (t == 0) {
        float lo4 = (float)p4bin * BINW;         // lower bound on p4
        float thresh = lo4 - 0.141422f;          // p4 - 0.1*sqrt(2), conservative
        int tb = (int)floorf(thresh * 1024.0f);
        if (tb < 0) tb = 0;
        stbin = tb;
        g_tbin[b] = tb;
    }
    __syncthreads();
    int tb = stbin;
    // bucket base (descending order): base[bin] = S[bin+1]
    if (4 * t     >= tb) g_pos[b][4 * t]     = S1;
    if (4 * t + 1 >= tb) g_pos[b][4 * t + 1] = S2;
    if (4 * t + 2 >= tb) g_pos[b][4 * t + 2] = S3;
    if (4 * t + 3 >= tb) g_pos[b][4 * t + 3] = excl;
    if (tb >= 4 * t && tb <= 4 * t + 3) {
        int Stb = (tb == 4 * t) ? S0 : (tb == 4 * t + 1) ? S1
                : (tb == 4 * t + 2) ? S2 : S3;
        g_ncand[b] = Stb;
    }
}

// -------- scatter: counting-sort into descending buckets + hist re-zero + pads --
__global__ void __launch_bounds__(256) scatter_kernel() {
    int i = blockIdx.x * 256 + threadIdx.x;
    // re-zero histogram for the next graph replay
    if (i < BS * NBIN) ((int*)g_hist)[i] = 0;
    // sentinel padding: w=-1e30 is provably rejected by the filter & break
    if (blockIdx.x < BS && threadIdx.x < 192) {
        int b = blockIdx.x;
        int idx = g_ncand[b] + threadIdx.x;
        g_cand4[b][idx] = make_float4(0.0f, 0.0f, 0.0f, -1e30f);
        g_candq[b][idx] = 0;
    }
    int b = i >> 14;
    float p = g_prob[i];
    int bin = min(NBIN - 1, (int)(p * 1024.0f));
    if (bin >= g_tbin[b]) {
        int slot = atomicAdd(&g_pos[b][bin], 1);
        g_cand4[b][slot] = g_packed[i];
        g_candq[b][slot] = i & (NQ - 1);
    }
}

// orderable-uint mapping and inverse
__device__ __forceinline__ unsigned int float_key(float f) {
    unsigned int u = __float_as_uint(f);
    return u ^ (((int)u < 0) ? 0xFFFFFFFFu : 0x80000000u);
}
__device__ __forceinline__ float key_to_float(unsigned int k) {
    return __uint_as_float(k ^ ((k & 0x80000000u) ? 0x80000000u : 0xFFFFFFFFu));
}

#define KEY_SENTINEL 0xFF7FFFFFFFFFFFFFull   // (float_key(FLT_MAX)<<32) | 0xFFFFFFFF

// snapshot-exchange merge with DEDUP insert: skips keys equal to any current
// entry, so overlapping lists (shared phase-1 prefix) merge correctly.
// If a global-top-4 key X is displaced from a lane's list, that lane holds 4
// keys < X which propagate into the merged result; hence the merged list is
// exactly the top-4 of the union of all lane lists.
#define DEDUP_MERGE(d)                                                         \
    {                                                                          \
        unsigned long long s0 = k0, s1 = k1, s2 = k2, s3 = k3;                 \
        unsigned long long p0 = __shfl_xor_sync(0xFFFFFFFFu, s0, d);           \
        unsigned long long p1 = __shfl_xor_sync(0xFFFFFFFFu, s1, d);           \
        unsigned long long p2 = __shfl_xor_sync(0xFFFFFFFFu, s2, d);           \
        unsigned long long p3 = __shfl_xor_sync(0xFFFFFFFFu, s3, d);           \
        unsigned long long ps[4] = {p0, p1, p2, p3};                           \
        _Pragma("unroll")                                                      \
        for (int r = 0; r < 4; r++) {                                          \
            unsigned long long pk = ps[r];                                     \
            if (pk < k3 && pk != k0 && pk != k1 && pk != k2) {                 \
                if (pk < k0)      { k3 = k2; k2 = k1; k1 = k0; k0 = pk; }      \
                else if (pk < k1) { k3 = k2; k2 = k1; k1 = pk; }               \
                else if (pk < k2) { k3 = k2; k2 = pk; }                        \
                else              { k3 = pk; }                                 \
            }                                                                  \
        }                                                                      \
    }

// evaluate one candidate f at index idx (sqrt-free filter + exact cost)
#define EVAL_CAND(f, idx)                                                      \
    {                                                                          \
        float h = __fmaf_rn((f).x, gx, __fmaf_rn((f).y, gy, (f).z));           \
        float u = __fmaf_rn(10.0f, (f).w, T);                                  \
        float v = __fmaf_rn(u, fabsf(u), -gg);                                 \
        if (h < v) {                                                           \
            float xx = __fmul_rn(-0.5f, (f).x), yy = __fmul_rn(-0.5f, (f).y);  \
            float d  = __fmaf_rn(yy, gy, __fmul_rn(xx, gx));                   \
            float s1 = __fadd_rn((f).z, gg);                                   \
            float sq = __fmaf_rn(-2.0f, d, s1);                                \
            float cost = __fadd_rn(                                            \
                __fmul_rn(COST_POINT, __fsqrt_rn(fmaxf(sq, 0.0f))), -(f).w);   \
            unsigned long long key =                                           \
                ((unsigned long long)float_key(cost) << 32)                    \
                | (unsigned int)__ldg(&candq[idx]);                            \
            if (key < k3) {                                                    \
                if (key < k0)      { k3 = k2; k2 = k1; k1 = k0; k0 = key; }    \
                else if (key < k1) { k3 = k2; k2 = k1; k1 = key; }             \
                else if (key < k2) { k3 = k2; k2 = key; }                      \
                else               { k3 = key; }                               \
                c3  = key_to_float((unsigned int)(k3 >> 32));                  \
                T   = __fmaf_rn(10.0f, c3, 1e-3f);                             \
                brk = __fadd_rn(-c3, -BINW);                                   \
            }                                                                  \
        }                                                                      \
    }

// -------- match: phase-1 (first 128 candidates, full merge -> tight global c3)
// then fully-independent per-lane scan (no shuffles), final dedup merge.
__global__ void __launch_bounds__(256) match_kernel(
    const float* __restrict__ pc,
    const float* __restrict__ gtc, const void* __restrict__ gtm)
{
    int blk = blockIdx.x;                 // 512 blocks: b*64 + sub
    int b   = blk >> 6;
    int sub = blk & 63;
    int t   = threadIdx.x;
    int par = t & 15;
    int g   = sub * 16 + (t >> 4);
    int bg  = b * NG + g;
    int active = mask_at(gtm, bg, g_mi32);
    int n = g_ncand[b];
    const float4* __restrict__ cand  = g_cand4[b];
    const int*    __restrict__ candq = g_candq[b];

    float2 gc = ((const float2*)gtc)[bg];
    float gx = gc.x, gy = gc.y;
    float gg = __fadd_rn(__fmul_rn(gx, gx), __fmul_rn(gy, gy));

    unsigned long long k0 = KEY_SENTINEL, k1 = KEY_SENTINEL,
                       k2 = KEY_SENTINEL, k3 = KEY_SENTINEL;
    float c3  = FLT_MAX;
    float T   = __fmaf_rn(10.0f, c3, 1e-3f);   // +inf: accept-all until filled
    float brk = -FLT_MAX;

    // ---- phase 1: window [0,128) — 8 candidates per lane
    {
        float4 fs[8];
        #pragma unroll
        for (int j = 0; j < 8; j++) fs[j] = __ldg(&cand[par + 16 * j]);
        if (active) {
            #pragma unroll
            for (int j = 0; j < 8; j++) EVAL_CAND(fs[j], par + 16 * j);
        }
    }
    // full merge: every lane now holds the exact global top-4 of window 0
    DEDUP_MERGE(1);
    DEDUP_MERGE(2);
    DEDUP_MERGE(4);
    DEDUP_MERGE(8);
    c3  = key_to_float((unsigned int)(k3 >> 32));
    T   = __fmaf_rn(10.0f, c3, 1e-3f);
    brk = __fadd_rn(-c3, -BINW);

    // ---- phase 2: independent per-lane scan, batches of 4, private break
    if (active) {
        for (int i = 128 + par; i < n; i += 64) {
            float4 f0 = __ldg(&cand[i]);
            float4 f1 = __ldg(&cand[i + 16]);
            float4 f2 = __ldg(&cand[i + 32]);
            float4 f3 = __ldg(&cand[i + 48]);
            // descending prob (granularity BINW): all elements after i have
            // prob < f0.w + BINW; if f0.w < brk they are all provably out.
            if (f0.w < brk) break;
            EVAL_CAND(f0, i);
            EVAL_CAND(f1, i + 16);
            EVAL_CAND(f2, i + 32);
            EVAL_CAND(f3, i + 48);
        }
    }

    // ---- final dedup merge of the 16 per-lane lists (overlap-safe)
    DEDUP_MERGE(1);
    DEDUP_MERGE(2);
    DEDUP_MERGE(4);
    DEDUP_MERGE(8);

    if (active && par == 0) {
        float acc = 0.0f;
        unsigned long long ks[4] = {k0, k1, k2, k3};
        #pragma unroll
        for (int k = 0; k < TOPK; k++) {
            int q = (int)(unsigned int)(ks[k] & 0xFFFFFFFFull);
            g_flag[b * NQ + q] = 1;          // idempotent; races benign
            float2 p = ((const float2*)pc)[b * NQ + q];   // exact coords
            float dx = __fadd_rn(p.x, -gx), dy = __fadd_rn(p.y, -gy);
            acc = __fadd_rn(acc, __fadd_rn(__fmul_rn(dx, dx), __fmul_rn(dy, dy)));
        }
        g_regp[bg] = acc;
    }
}

// -------- reduce: 512 blocks, 1 element/thread (spreads MUFU latency),
//          rg/cn in first 32 blocks; last-block fixed-order finale --------
__global__ void __launch_bounds__(256) reduce_kernel(
    const float* __restrict__ pl, const void* __restrict__ gtm,
    float* __restrict__ out)
{
    int blk = blockIdx.x;
    int t = threadIdx.x;
    int i = blk * 256 + t;
    int mi32 = g_mi32;

    // cls: one element per thread (log-softmax recomputed, literal formula)
    float2 lg = ((const float2*)pl)[i];
    float l0 = lg.x, l1 = lg.y;
    float mm = fmaxf(l0, l1);
    float ls = logf(__fadd_rn(expf(l0 - mm), expf(l1 - mm)));
    float lsel = g_flag[i] ? l0 : l1;
    float cl = __fadd_rn(__fadd_rn(lsel, -mm), -ls);

    float rg = 0.0f; int cn = 0;
    if (i < NBG) {
        rg = g_regp[i];
        cn = mask_at(gtm, i, mi32);
    }

    __shared__ float s1[256], s2[256];
    __shared__ int   s3[256];
    s1[t] = cl; s2[t] = rg; s3[t] = cn;
    __syncthreads();
    for (int s = 128; s > 0; s >>= 1) {
        if (t < s) { s1[t] += s1[t + s]; s2[t] += s2[t + s]; s3[t] += s3[t + s]; }
        __syncthreads();
    }
    __shared__ bool s_last;
    if (t == 0) {
        g_part[blk]            = s1[0];
        g_part[NRED + blk]     = s2[0];
        g_part[2 * NRED + blk] = (float)s3[0];
        __threadfence();
        int old = atomicAdd(&g_done, 1);
        s_last = (old == NRED - 1);
    }
    __syncthreads();
    if (s_last) {
        // fixed-order combine of 512 partials (2 per thread, then tree)
        float a  = g_part[t]            + g_part[t + 256];
        float bb = g_part[NRED + t]     + g_part[NRED + t + 256];
        float cc = g_part[2 * NRED + t] + g_part[2 * NRED + t + 256];
        s1[t] = a; s2[t] = bb; s3[t] = 0;
        __shared__ float s4[256];
        s4[t] = cc;
        __syncthreads();
        for (int s = 128; s > 0; s >>= 1) {
            if (t < s) { s1[t] += s1[t + s]; s2[t] += s2[t + s]; s4[t] += s4[t + s]; }
            __syncthreads();
        }
        if (t == 0) {
            float n_valid = __fmul_rn(s4[0], (float)TOPK);
            out[0] = __fmul_rn(__fdiv_rn(s2[0], __fmul_rn(n_valid, 2.0f)), REG_COEF);
            out[1] = __fdiv_rn(-s1[0], (float)NTOT);
        }
    }
}

extern "C" void kernel_launch(void* const* d_in, const int* in_sizes, int n_in,
                              void* d_out, int out_size)
{
    (void)in_sizes; (void)n_in; (void)out_size;
    const float* pred_coords = (const float*)d_in[0];
    const float* pred_logits = (const float*)d_in[1];
    const float* gt_coords   = (const float*)d_in[2];
    const void*  gt_masks    = d_in[4];
    float* out = (float*)d_out;

    prep_kernel   <<<NTOT / 256, 256>>>(pred_coords, pred_logits,
                                        (const unsigned char*)gt_masks);
    setup_kernel  <<<BS, 256>>>();
    scatter_kernel<<<NTOT / 256, 256>>>();
    match_kernel  <<<BS * 64, 256>>>(pred_coords, gt_coords, gt_masks);
    reduce_kernel <<<NRED, 256>>>(pred_logits, gt_masks, out);
}